// round 3
// baseline (speedup 1.0000x reference)
#include <cuda_runtime.h>
#include <cstddef>
#include <cstdint>

#define T_STEPS   4096
#define H_DIM     512
#define N_BATCH   32
#define V_DIM     3

#define GROUPS    4      // independent batch groups
#define BPG       8      // batches per group
#define COL_CTAS  32     // column CTAs per group
#define COLS      16     // H columns per CTA
#define NTHREADS  256
#define NWARPS    8
#define KCHUNK    (H_DIM / NWARPS)   // 64 k per warp

// ---- persistent scratch (no allocation allowed) ----
// double-buffered state: step t reads buf[t&1], writes buf[(t+1)&1]
__device__ __align__(32) float g_state[2][GROUPS][H_DIM][BPG];  // 128KB
__device__ int g_bar[GROUPS][T_STEPS];                          // arrive counters

// Reset per replay: state buf := 0.01 (both buffers, harmless), barriers := 0
__global__ void esn_reset_kernel() {
    int idx = blockIdx.x * blockDim.x + threadIdx.x;   // 0 .. 32767
    ((float*)g_state)[idx] = 0.01f;
    if (idx < GROUPS * T_STEPS) ((int*)g_bar)[idx] = 0;
}

__device__ __forceinline__ uint64_t packdup(float v) {
    uint64_t r;
    asm("mov.b64 %0, {%1, %1};" : "=l"(r) : "f"(v));
    return r;
}
#define FMA2(acc, a, b) \
    asm("fma.rn.f32x2 %0, %1, %2, %0;" : "+l"(acc) : "l"(a), "l"(b))

// smem: reduction buffer only
// red[8 warps][8 batches][16 cols]
#define SMEM_BYTES (NWARPS * BPG * COLS * 4)

__global__ __launch_bounds__(NTHREADS, 1)
void esn_kernel(const float* __restrict__ X,
                const float* __restrict__ W_in,
                const float* __restrict__ W_int,
                const float* __restrict__ noise,
                float* __restrict__ out)
{
    extern __shared__ float smem[];
    float (*red)[BPG][COLS] = (float(*)[BPG][COLS])smem;

    const int tid   = threadIdx.x;
    const int g     = blockIdx.x >> 5;        // batch group 0..3
    const int cbase = (blockIdx.x & 31) * COLS;
    const int w     = tid >> 5;               // warp -> 64-k chunk
    const int lane  = tid & 31;

    // compute-lane decomposition: j2 = 2-col slot (0..7), kg = 16-k subchunk (0..3)
    const int j2 = lane & 7;
    const int kg = lane >> 3;
    const int kbase = w * KCHUNK + kg * 16;   // this lane's first k

    // ---- one-time: W slice into registers, duplicated f32x2 packs ----
    // wp[kk][j] covers W_int[kbase+kk][cbase + j2*2 + j]
    uint64_t wp[16][2];
    #pragma unroll
    for (int kk = 0; kk < 16; ++kk) {
        #pragma unroll
        for (int j = 0; j < 2; ++j) {
            float wv = __ldg(&W_int[(size_t)(kbase + kk) * H_DIM + cbase + j2 * 2 + j]);
            wp[kk][j] = packdup(wv);
        }
    }

    // reducer-role constants (threads 0..127)
    const int rb = tid >> 4;             // batch-in-group
    const int rj = tid & 15;             // column-in-slice
    const int gb = g * BPG + rb;         // global batch
    const int h  = cbase + rj;           // global column
    float wi0 = 0.f, wi1 = 0.f, wi2 = 0.f;
    if (tid < 128) {
        wi0 = __ldg(&W_in[(size_t)h * V_DIM + 0]);
        wi1 = __ldg(&W_in[(size_t)h * V_DIM + 1]);
        wi2 = __ldg(&W_in[(size_t)h * V_DIM + 2]);
    }

    for (int t = 0; t < T_STEPS; ++t) {
        const float* srd = &g_state[t & 1][g][0][0];
        float*       swr = &g_state[(t & 1) ^ 1][g][0][0];

        // ---- prefetch noise & X (independent of state; issued before poll) ----
        float nval = 0.f, x0 = 0.f, x1 = 0.f, x2 = 0.f;
        if (tid < 128) {
            nval = __ldg(noise + ((size_t)t * N_BATCH + gb) * H_DIM + h);
            const float* xp = X + ((size_t)gb * T_STEPS + t) * V_DIM;
            x0 = __ldg(xp + 0); x1 = __ldg(xp + 1); x2 = __ldg(xp + 2);
        }

        // ---- per-warp acquire-poll: wait for state_{t-1} from all 32 CTAs ----
        if (t > 0) {
            const int* barp = &g_bar[g][t - 1];
            int v;
            do {
                asm volatile("ld.acquire.gpu.global.b32 %0, [%1];"
                             : "=r"(v) : "l"(barp) : "memory");
            } while (v < COL_CTAS);
        }

        // ---- compute: state read direct from L2 (.cg), packed f32x2 FMA ----
        // acc[bp][j]: f32x2 over batch pair (2bp, 2bp+1), col (j2*2+j)
        uint64_t acc[4][2];
        #pragma unroll
        for (int bp = 0; bp < 4; ++bp) { acc[bp][0] = 0ull; acc[bp][1] = 0ull; }

        const char* sb = (const char*)srd + (size_t)kbase * (BPG * 4);
        #pragma unroll
        for (int kk = 0; kk < 16; ++kk) {
            uint64_t s01, s23, s45, s67;
            asm volatile("ld.global.cg.v2.u64 {%0, %1}, [%2];"
                         : "=l"(s01), "=l"(s23) : "l"(sb + kk * 32) : "memory");
            asm volatile("ld.global.cg.v2.u64 {%0, %1}, [%2];"
                         : "=l"(s45), "=l"(s67) : "l"(sb + kk * 32 + 16) : "memory");
            FMA2(acc[0][0], s01, wp[kk][0]);  FMA2(acc[0][1], s01, wp[kk][1]);
            FMA2(acc[1][0], s23, wp[kk][0]);  FMA2(acc[1][1], s23, wp[kk][1]);
            FMA2(acc[2][0], s45, wp[kk][0]);  FMA2(acc[2][1], s45, wp[kk][1]);
            FMA2(acc[3][0], s67, wp[kk][0]);  FMA2(acc[3][1], s67, wp[kk][1]);
        }

        // unpack to scalars: a[bp][j][h] = partial for batch 2bp+h, col j2*2+j
        float a[4][2][2];
        #pragma unroll
        for (int bp = 0; bp < 4; ++bp)
            #pragma unroll
            for (int j = 0; j < 2; ++j)
                asm("mov.b64 {%0, %1}, %2;"
                    : "=f"(a[bp][j][0]), "=f"(a[bp][j][1]) : "l"(acc[bp][j]));

        // reduce the 4 kg subchunks within the warp (xor 8, xor 16)
        #pragma unroll
        for (int bp = 0; bp < 4; ++bp)
            #pragma unroll
            for (int j = 0; j < 2; ++j)
                #pragma unroll
                for (int hh = 0; hh < 2; ++hh) {
                    float v = a[bp][j][hh];
                    v += __shfl_xor_sync(0xffffffffu, v, 8);
                    v += __shfl_xor_sync(0xffffffffu, v, 16);
                    a[bp][j][hh] = v;
                }

        if (kg == 0) {
            #pragma unroll
            for (int bp = 0; bp < 4; ++bp)
                #pragma unroll
                for (int j = 0; j < 2; ++j)
                    #pragma unroll
                    for (int hh = 0; hh < 2; ++hh)
                        red[w][bp * 2 + hh][j2 * 2 + j] = a[bp][j][hh];
        }
        __syncthreads();

        // ---- reduce across 8 warps, add input + noise, tanh, write ----
        if (tid < 128) {
            float sum = 0.f;
            #pragma unroll
            for (int ww = 0; ww < NWARPS; ++ww) sum += red[ww][rb][rj];
            float pre = sum + x0 * wi0 + x1 * wi1 + x2 * wi2 + 0.01f * nval;
            float sv  = tanhf(pre);
            swr[(size_t)h * BPG + rb] = sv;                           // next-step state
            out[((size_t)gb * T_STEPS + t) * H_DIM + h] = sv;         // output (N,T,H)
        }
        __syncthreads();

        // ---- release arrive (fence makes CTA's writes visible, then flag) ----
        if (tid == 0) {
            __threadfence();
            atomicAdd(&g_bar[g][t], 1);
        }
    }
}

extern "C" void kernel_launch(void* const* d_in, const int* in_sizes, int n_in,
                              void* d_out, int out_size)
{
    const float* X     = (const float*)d_in[0];   // (32, 4096, 3)
    const float* W_in  = (const float*)d_in[1];   // (512, 3)
    const float* W_int = (const float*)d_in[2];   // (512, 512)
    const float* noise = (const float*)d_in[3];   // (4096, 32, 512)
    float* out = (float*)d_out;                   // (32, 4096, 512)

    cudaFuncSetAttribute(esn_kernel, cudaFuncAttributeMaxDynamicSharedMemorySize, SMEM_BYTES);

    esn_reset_kernel<<<64, 512>>>();
    esn_kernel<<<GROUPS * COL_CTAS, NTHREADS, SMEM_BYTES>>>(X, W_in, W_int, noise, out);
}

// round 4
// speedup vs baseline: 1.1776x; 1.1776x over previous
#include <cuda_runtime.h>
#include <cstddef>
#include <cstdint>

#define T_STEPS   4096
#define H_DIM     512
#define N_BATCH   32
#define V_DIM     3

#define GROUPS    4      // independent batch groups
#define BPG       8      // batches per group
#define COL_CTAS  32     // column CTAs per group
#define COLS      16     // H columns per CTA
#define NTHREADS  256
#define NWARPS    8
#define KCHUNK    (H_DIM / NWARPS)   // 64 k per warp

// ---- persistent scratch (no allocation allowed) ----
// double-buffered state: step t reads buf[t&1], writes buf[(t+1)&1]
__device__ __align__(32) float g_state[2][GROUPS][H_DIM][BPG];  // 128KB
__device__ int g_bar[GROUPS][T_STEPS];                          // arrive counters

// Reset per replay: state := 0.01 (both buffers), barriers := 0
__global__ void esn_reset_kernel() {
    int idx = blockIdx.x * blockDim.x + threadIdx.x;   // 0 .. 32767
    ((float*)g_state)[idx] = 0.01f;
    if (idx < GROUPS * T_STEPS) ((int*)g_bar)[idx] = 0;
}

__device__ __forceinline__ uint64_t packdup(float v) {
    uint64_t r;
    asm("mov.b64 %0, {%1, %1};" : "=l"(r) : "f"(v));
    return r;
}
#define FMA2(acc, a, b) \
    asm("fma.rn.f32x2 %0, %1, %2, %0;" : "+l"(acc) : "l"(a), "l"(b))

// dynamic smem layout (floats):
// [0, 4096)        s_sm[512][8]   (state stage, 16KB)
// [4096, 5120)     red[8][8][16]  (warp partials, 4KB)
#define SMEM_FLOATS (4096 + 1024)
#define SMEM_BYTES  (SMEM_FLOATS * 4)

__global__ __launch_bounds__(NTHREADS, 1)
void esn_kernel(const float* __restrict__ X,
                const float* __restrict__ W_in,
                const float* __restrict__ W_int,
                const float* __restrict__ noise,
                float* __restrict__ out)
{
    extern __shared__ float smem[];
    float (*s_sm)[BPG]      = (float(*)[BPG])      smem;
    float (*red)[BPG][COLS] = (float(*)[BPG][COLS])(smem + 4096);

    const int tid   = threadIdx.x;
    const int g     = blockIdx.x >> 5;        // batch group 0..3
    const int cbase = (blockIdx.x & 31) * COLS;
    const int w     = tid >> 5;               // warp -> 64-k chunk
    const int lane  = tid & 31;

    // compute-lane decomposition: j2 = col pair (0..7), kg = 16-k subchunk (0..3)
    const int j2 = lane & 7;
    const int kg = lane >> 3;
    const int kbase = w * KCHUNK + kg * 16;

    // ---- one-time: W slice into registers as duplicated f32x2 packs ----
    uint64_t wp[16][2];
    #pragma unroll
    for (int kk = 0; kk < 16; ++kk) {
        #pragma unroll
        for (int j = 0; j < 2; ++j) {
            float wv = __ldg(&W_int[(size_t)(kbase + kk) * H_DIM + cbase + j2 * 2 + j]);
            wp[kk][j] = packdup(wv);
        }
    }

    // reducer-role constants (threads 0..127)
    const int rb = tid >> 4;             // batch-in-group
    const int rj = tid & 15;             // column-in-slice
    const int gb = g * BPG + rb;         // global batch
    const int h  = cbase + rj;           // global column
    float wi0 = 0.f, wi1 = 0.f, wi2 = 0.f;
    if (tid < 128) {
        wi0 = __ldg(&W_in[(size_t)h * V_DIM + 0]);
        wi1 = __ldg(&W_in[(size_t)h * V_DIM + 1]);
        wi2 = __ldg(&W_in[(size_t)h * V_DIM + 2]);
    }

    for (int t = 0; t < T_STEPS; ++t) {
        const float* srd = &g_state[t & 1][g][0][0];
        float*       swr = &g_state[(t & 1) ^ 1][g][0][0];

        // ---- prefetch noise & X (independent of state; issued before poll) ----
        float nval = 0.f, x0 = 0.f, x1 = 0.f, x2 = 0.f;
        if (tid < 128) {
            nval = __ldg(noise + ((size_t)t * N_BATCH + gb) * H_DIM + h);
            const float* xp = X + ((size_t)gb * T_STEPS + t) * V_DIM;
            x0 = __ldg(xp + 0); x1 = __ldg(xp + 1); x2 = __ldg(xp + 2);
        }

        // ---- per-warp acquire-poll: wait for state_{t-1} from all 32 CTAs ----
        if (t > 0) {
            const int* barp = &g_bar[g][t - 1];
            int v;
            do {
                asm volatile("ld.acquire.gpu.global.b32 %0, [%1];"
                             : "=r"(v) : "l"(barp) : "memory");
            } while (v < COL_CTAS);
        }

        // ---- per-warp state stage (own 64-k slice; L2-resident via .cg) ----
        {
            const float4* src = (const float4*)srd + w * 128 + lane;
            float4*       dst = (float4*)(&s_sm[0][0]) + w * 128 + lane;
            #pragma unroll
            for (int i = 0; i < 4; ++i) {
                float4 v4 = __ldcg(src + i * 32);
                dst[i * 32] = v4;
            }
            __syncwarp();
        }

        // ---- packed f32x2 compute: 8 acc = 4 batch-pairs x 2 cols ----
        uint64_t acc[4][2];
        #pragma unroll
        for (int bp = 0; bp < 4; ++bp) { acc[bp][0] = 0ull; acc[bp][1] = 0ull; }

        const ulonglong2* srow = (const ulonglong2*)&s_sm[kbase][0]; // 2 per k-row
        #pragma unroll
        for (int kk = 0; kk < 16; ++kk) {
            ulonglong2 p0 = srow[kk * 2 + 0];   // batches 0-3 (two f32x2)
            ulonglong2 p1 = srow[kk * 2 + 1];   // batches 4-7
            FMA2(acc[0][0], p0.x, wp[kk][0]);  FMA2(acc[0][1], p0.x, wp[kk][1]);
            FMA2(acc[1][0], p0.y, wp[kk][0]);  FMA2(acc[1][1], p0.y, wp[kk][1]);
            FMA2(acc[2][0], p1.x, wp[kk][0]);  FMA2(acc[2][1], p1.x, wp[kk][1]);
            FMA2(acc[3][0], p1.y, wp[kk][0]);  FMA2(acc[3][1], p1.y, wp[kk][1]);
        }

        // unpack: a[bp][j][hh] = partial for batch 2bp+hh, col j2*2+j
        float a[4][2][2];
        #pragma unroll
        for (int bp = 0; bp < 4; ++bp)
            #pragma unroll
            for (int j = 0; j < 2; ++j)
                asm("mov.b64 {%0, %1}, %2;"
                    : "=f"(a[bp][j][0]), "=f"(a[bp][j][1]) : "l"(acc[bp][j]));

        // reduce the 4 kg subchunks within the warp (xor 8, xor 16)
        #pragma unroll
        for (int bp = 0; bp < 4; ++bp)
            #pragma unroll
            for (int j = 0; j < 2; ++j)
                #pragma unroll
                for (int hh = 0; hh < 2; ++hh) {
                    float v = a[bp][j][hh];
                    v += __shfl_xor_sync(0xffffffffu, v, 8);
                    v += __shfl_xor_sync(0xffffffffu, v, 16);
                    a[bp][j][hh] = v;
                }

        if (kg == 0) {
            #pragma unroll
            for (int bp = 0; bp < 4; ++bp)
                #pragma unroll
                for (int hh = 0; hh < 2; ++hh)
                    *(float2*)&red[w][bp * 2 + hh][j2 * 2] =
                        make_float2(a[bp][0][hh], a[bp][1][hh]);
        }
        __syncthreads();

        // ---- reduce across 8 warps, add input + noise, tanh, write ----
        if (tid < 128) {
            float sum = 0.f;
            #pragma unroll
            for (int ww = 0; ww < NWARPS; ++ww) sum += red[ww][rb][rj];
            float pre = sum + x0 * wi0 + x1 * wi1 + x2 * wi2 + 0.01f * nval;
            float sv  = tanhf(pre);
            swr[(size_t)h * BPG + rb] = sv;                           // next-step state
            out[((size_t)gb * T_STEPS + t) * H_DIM + h] = sv;         // output (N,T,H)
        }
        __syncthreads();

        // ---- release arrive (fence makes CTA's writes visible, then flag) ----
        if (tid == 0) {
            __threadfence();
            atomicAdd(&g_bar[g][t], 1);
        }
    }
}

extern "C" void kernel_launch(void* const* d_in, const int* in_sizes, int n_in,
                              void* d_out, int out_size)
{
    const float* X     = (const float*)d_in[0];   // (32, 4096, 3)
    const float* W_in  = (const float*)d_in[1];   // (512, 3)
    const float* W_int = (const float*)d_in[2];   // (512, 512)
    const float* noise = (const float*)d_in[3];   // (4096, 32, 512)
    float* out = (float*)d_out;                   // (32, 4096, 512)

    cudaFuncSetAttribute(esn_kernel, cudaFuncAttributeMaxDynamicSharedMemorySize, SMEM_BYTES);

    esn_reset_kernel<<<64, 512>>>();
    esn_kernel<<<GROUPS * COL_CTAS, NTHREADS, SMEM_BYTES>>>(X, W_in, W_int, noise, out);
}